// round 2
// baseline (speedup 1.0000x reference)
#include <cuda_runtime.h>

#define DIMX 1024
#define NEXP 8
#define HIDX 4096
#define TTOK 4096   // B*S = 2*2048

// ---------------- static scratch (no allocations allowed) ----------------
__device__ signed char g_wq1[(size_t)NEXP * HIDX * DIMX];   // ternary w1, 33.5MB
__device__ signed char g_wq2[(size_t)NEXP * DIMX * HIDX];   // ternary w2, 33.5MB
__device__ signed char g_wqr[NEXP * DIMX];
__device__ signed char g_wqn[NEXP * DIMX];
__device__ float g_partial[18 * 64];
__device__ float g_mval[18];                                 // dequant scales (mean|w| clipped)
__device__ signed char g_xq[(size_t)TTOK * DIMX];            // int8 activations
__device__ float g_deqx[TTOK];                               // per-token dequant
__device__ int   g_cnt[NEXP];
__device__ int   g_off[NEXP];
__device__ int   g_tok[NEXP * TTOK];
__device__ float g_gate[NEXP * TTOK];
__device__ float g_h[(size_t)2 * TTOK * HIDX];               // fp32 hidden, 134MB
__device__ signed char g_hq[(size_t)2 * TTOK * HIDX];        // int8 hidden
__device__ float g_deqh[2 * TTOK];

// ---------------- helpers ----------------
__device__ __forceinline__ signed char terq(float x) {
    float r = rintf(x);
    r = fminf(1.f, fmaxf(-1.f, r));
    return (signed char)(int)r;
}
__device__ __forceinline__ signed char qi8(float x) {
    float r = rintf(x);
    r = fminf(127.f, fmaxf(-128.f, r));
    return (signed char)(int)r;
}

// ---------------- weight stats: sum |w| per tensor/expert ----------------
__global__ void stats_partial(const float* __restrict__ wr, const float* __restrict__ wn,
                              const float* __restrict__ w1, const float* __restrict__ w2) {
    int slot = blockIdx.y, chunk = blockIdx.x;
    const float4* p;
    int nvec;
    if (slot < 2) {
        if (chunk != 0) return;
        p = (const float4*)(slot ? wn : wr);
        nvec = NEXP * DIMX / 4;
    } else if (slot < 10) {
        p = (const float4*)(w1 + (size_t)(slot - 2) * HIDX * DIMX) + (size_t)chunk * 16384;
        nvec = 16384;
    } else {
        p = (const float4*)(w2 + (size_t)(slot - 10) * DIMX * HIDX) + (size_t)chunk * 16384;
        nvec = 16384;
    }
    float s = 0.f;
    for (int i = threadIdx.x; i < nvec; i += 256) {
        float4 v = p[i];
        s += fabsf(v.x) + fabsf(v.y) + fabsf(v.z) + fabsf(v.w);
    }
    __shared__ float sh[8];
    #pragma unroll
    for (int o = 16; o; o >>= 1) s += __shfl_xor_sync(0xffffffffu, s, o);
    if ((threadIdx.x & 31) == 0) sh[threadIdx.x >> 5] = s;
    __syncthreads();
    if (threadIdx.x == 0) {
        float t = 0.f;
        #pragma unroll
        for (int j = 0; j < 8; j++) t += sh[j];
        g_partial[slot * 64 + chunk] = t;
    }
}

__global__ void stats_final() {
    int s = threadIdx.x;
    if (s >= 18) return;
    int nc = (s < 2) ? 1 : 64;
    float sum = 0.f;
    for (int c = 0; c < nc; c++) sum += g_partial[s * 64 + c];
    float nelem = (s < 2) ? (float)(NEXP * DIMX) : (float)((size_t)HIDX * DIMX);
    g_mval[s] = fmaxf(sum / nelem, 1e-5f);
}

// ---------------- weight ternarization ----------------
__global__ void wquant_small(const float* __restrict__ wr, const float* __restrict__ wn) {
    int i = blockIdx.x * 256 + threadIdx.x;   // 0 .. 16383
    if (i < NEXP * DIMX) {
        float sc = 1.0f / g_mval[0];
        g_wqr[i] = terq(wr[i] * sc);
    } else {
        int j = i - NEXP * DIMX;
        float sc = 1.0f / g_mval[1];
        g_wqn[j] = terq(wn[j] * sc);
    }
}

__global__ void wquant_big(const float* __restrict__ w, int which) {
    size_t i = (size_t)blockIdx.x * 256 + threadIdx.x;   // float4 index
    const size_t nvec = (size_t)NEXP * HIDX * DIMX / 4;  // 8388608
    if (i >= nvec) return;
    int e = (int)(i >> 20);                              // 1048576 float4 per expert
    float sc = 1.0f / g_mval[(which == 1 ? 2 : 10) + e];
    float4 v = ((const float4*)w)[i];
    char4 c;
    c.x = terq(v.x * sc); c.y = terq(v.y * sc); c.z = terq(v.z * sc); c.w = terq(v.w * sc);
    signed char* dst = (which == 1) ? g_wq1 : g_wq2;
    ((char4*)dst)[i] = c;
}

// ---------------- activation quant (rmsnorm + int8 absmax) ----------------
__global__ void act_quant(const float* __restrict__ x) {
    int t = blockIdx.x;
    int tid = threadIdx.x;
    float4 v = ((const float4*)(x + (size_t)t * DIMX))[tid];
    float ss = v.x * v.x + v.y * v.y + v.z * v.z + v.w * v.w;
    float am = fmaxf(fmaxf(fabsf(v.x), fabsf(v.y)), fmaxf(fabsf(v.z), fabsf(v.w)));
    __shared__ float shs[8], shm[8];
    #pragma unroll
    for (int o = 16; o; o >>= 1) {
        ss += __shfl_xor_sync(0xffffffffu, ss, o);
        am = fmaxf(am, __shfl_xor_sync(0xffffffffu, am, o));
    }
    if ((tid & 31) == 0) { shs[tid >> 5] = ss; shm[tid >> 5] = am; }
    __syncthreads();
    float tss = 0.f, tam = 0.f;
    #pragma unroll
    for (int j = 0; j < 8; j++) { tss += shs[j]; tam = fmaxf(tam, shm[j]); }
    float rs = rsqrtf(tss / (float)DIMX + 1e-6f);
    float a = fmaxf(tam * rs, 1e-5f);
    float sc = 127.0f / a;
    if (tid == 0) g_deqx[t] = a / 127.0f;
    char4 c;
    c.x = qi8(v.x * rs * sc); c.y = qi8(v.y * rs * sc);
    c.z = qi8(v.z * rs * sc); c.w = qi8(v.w * rs * sc);
    ((char4*)(g_xq + (size_t)t * DIMX))[tid] = c;
}

// ---------------- router: 16 dp4a dots, noisy top-2, gates, expert lists ----------------
__global__ void router_kernel(const float* __restrict__ eps) {
    int t = blockIdx.x * 8 + (threadIdx.x >> 5);
    int lane = threadIdx.x & 31;
    const int* xp = (const int*)(g_xq + (size_t)t * DIMX);
    int xi[8];
    #pragma unroll
    for (int j = 0; j < 8; j++) xi[j] = xp[lane + 32 * j];
    float dq = g_deqx[t];
    float vals[NEXP];
    #pragma unroll
    for (int e = 0; e < NEXP; e++) {
        const int* wrp = (const int*)(g_wqr + e * DIMX);
        const int* wnp = (const int*)(g_wqn + e * DIMX);
        int ar = 0, an = 0;
        #pragma unroll
        for (int j = 0; j < 8; j++) {
            ar = __dp4a(xi[j], wrp[lane + 32 * j], ar);
            an = __dp4a(xi[j], wnp[lane + 32 * j], an);
        }
        #pragma unroll
        for (int o = 16; o; o >>= 1) {
            ar += __shfl_xor_sync(0xffffffffu, ar, o);
            an += __shfl_xor_sync(0xffffffffu, an, o);
        }
        if (lane == 0) {
            float lg = (float)ar * dq * g_mval[0];
            float nl = (float)an * dq * g_mval[1];
            float sp = fmaxf(nl, 0.f) + log1pf(expf(-fabsf(nl)));   // softplus (stable)
            vals[e] = lg + eps[t * NEXP + e] * sp;
        }
    }
    if (lane == 0) {
        float v0 = -1e30f, v1 = -1e30f;
        int i0 = 0, i1 = 0;
        #pragma unroll
        for (int e = 0; e < NEXP; e++) {
            float v = vals[e];
            if (v > v0) { v1 = v0; i1 = i0; v0 = v; i0 = e; }
            else if (v > v1) { v1 = v; i1 = e; }
        }
        float ex = expf(v1 - v0);
        float inv = 1.0f / (1.0f + ex);
        float g0 = inv, g1 = ex * inv;
        int p0 = atomicAdd(&g_cnt[i0], 1);
        g_tok[i0 * TTOK + p0] = t;
        g_gate[i0 * TTOK + p0] = g0;
        int p1 = atomicAdd(&g_cnt[i1], 1);
        g_tok[i1 * TTOK + p1] = t;
        g_gate[i1 * TTOK + p1] = g1;
    }
}

__global__ void zero_cnt() { if (threadIdx.x < NEXP) g_cnt[threadIdx.x] = 0; }

__global__ void scan_off() {
    if (threadIdx.x == 0) {
        int o = 0;
        for (int e = 0; e < NEXP; e++) { g_off[e] = o; o += g_cnt[e]; }
    }
}

// ---------------- per-row hidden quant (rmsnorm + int8) ----------------
__global__ void h_quant() {
    int e = blockIdx.y, pos = blockIdx.x;
    if (pos >= g_cnt[e]) return;
    size_t row = (size_t)g_off[e] + pos;
    const float4* hp = (const float4*)(g_h + row * HIDX);
    int tid = threadIdx.x;
    float4 r[4];
    float ss = 0.f, am = 0.f;
    #pragma unroll
    for (int j = 0; j < 4; j++) {
        r[j] = hp[tid + 256 * j];
        ss += r[j].x * r[j].x + r[j].y * r[j].y + r[j].z * r[j].z + r[j].w * r[j].w;
        am = fmaxf(am, fmaxf(fmaxf(fabsf(r[j].x), fabsf(r[j].y)), fmaxf(fabsf(r[j].z), fabsf(r[j].w))));
    }
    __shared__ float shs[8], shm[8];
    #pragma unroll
    for (int o = 16; o; o >>= 1) {
        ss += __shfl_xor_sync(0xffffffffu, ss, o);
        am = fmaxf(am, __shfl_xor_sync(0xffffffffu, am, o));
    }
    if ((tid & 31) == 0) { shs[tid >> 5] = ss; shm[tid >> 5] = am; }
    __syncthreads();
    float tss = 0.f, tam = 0.f;
    #pragma unroll
    for (int j = 0; j < 8; j++) { tss += shs[j]; tam = fmaxf(tam, shm[j]); }
    float rs = rsqrtf(tss / (float)HIDX + 1e-6f);
    float a = fmaxf(tam * rs, 1e-5f);
    float sc = 127.0f / a;
    if (tid == 0) g_deqh[row] = a / 127.0f;
    char4* dst = (char4*)(g_hq + row * HIDX);
    #pragma unroll
    for (int j = 0; j < 4; j++) {
        char4 c;
        c.x = qi8(r[j].x * rs * sc); c.y = qi8(r[j].y * rs * sc);
        c.z = qi8(r[j].z * rs * sc); c.w = qi8(r[j].w * rs * sc);
        dst[tid + 256 * j] = c;
    }
}

// ---------------- int8 tensor-core grouped GEMM ----------------
#define BM 128
#define BN 128
#define BKK 64
#define LDSS 80   // 64 + 16 pad: conflict-free fragment reads

__device__ __forceinline__ void mma8(int (&c)[4], const unsigned (&a)[4], const unsigned (&b)[2]) {
    asm volatile(
        "mma.sync.aligned.m16n8k32.row.col.s32.s8.s8.s32 "
        "{%0,%1,%2,%3}, {%4,%5,%6,%7}, {%8,%9}, {%0,%1,%2,%3};\n"
        : "+r"(c[0]), "+r"(c[1]), "+r"(c[2]), "+r"(c[3])
        : "r"(a[0]), "r"(a[1]), "r"(a[2]), "r"(a[3]), "r"(b[0]), "r"(b[1]));
}

template <int MODE>
__global__ __launch_bounds__(256) void bit_gemm(float* __restrict__ out) {
    constexpr int K = (MODE == 1) ? DIMX : HIDX;
    constexpr int N = (MODE == 1) ? HIDX : DIMX;
    const int e = blockIdx.z;
    const int cnt = g_cnt[e];
    const int m0 = blockIdx.y * BM;
    if (m0 >= cnt) return;
    const int n0 = blockIdx.x * BN;
    const int off = g_off[e];

    __shared__ signed char sA[BM * LDSS];
    __shared__ signed char sB[BN * LDSS];

    const int tid = threadIdx.x;
    const int lane = tid & 31, warp = tid >> 5;
    const int wm = warp >> 2, wn = warp & 3;   // 2x4 warp grid

    int acc[4][4][4];
    #pragma unroll
    for (int a = 0; a < 4; a++)
        #pragma unroll
        for (int b = 0; b < 4; b++)
            #pragma unroll
            for (int c = 0; c < 4; c++) acc[a][b][c] = 0;

    const int lr = tid >> 1;
    const int lcb = (tid & 1) * 32;
    const bool aok = (m0 + lr) < cnt;
    const signed char* Ap;
    if (MODE == 1) {
        int tok = aok ? g_tok[e * TTOK + m0 + lr] : 0;
        Ap = g_xq + (size_t)tok * K + lcb;
    } else {
        int r = aok ? (off + m0 + lr) : 0;
        Ap = g_hq + (size_t)r * K + lcb;
    }
    const signed char* wsrc = (MODE == 1) ? g_wq1 : g_wq2;
    const signed char* Bp = wsrc + (size_t)e * N * K + (size_t)(n0 + lr) * K + lcb;

    signed char* sArow = sA + lr * LDSS + lcb;
    signed char* sBrow = sB + lr * LDSS + lcb;

    for (int kb = 0; kb < K; kb += BKK) {
        int4 a0 = make_int4(0, 0, 0, 0), a1 = a0;
        if (aok) {
            a0 = *(const int4*)(Ap + kb);
            a1 = *(const int4*)(Ap + kb + 16);
        }
        int4 b0 = *(const int4*)(Bp + kb);
        int4 b1 = *(const int4*)(Bp + kb + 16);
        __syncthreads();
        *(int4*)(sArow) = a0;
        *(int4*)(sArow + 16) = a1;
        *(int4*)(sBrow) = b0;
        *(int4*)(sBrow + 16) = b1;
        __syncthreads();

        #pragma unroll
        for (int ks = 0; ks < 2; ks++) {
            unsigned af[4][4];
            #pragma unroll
            for (int mi = 0; mi < 4; mi++) {
                const signed char* p = sA + (wm * 64 + mi * 16 + (lane >> 2)) * LDSS + ks * 32 + (lane & 3) * 4;
                af[mi][0] = *(const unsigned*)p;
                af[mi][1] = *(const unsigned*)(p + 8 * LDSS);
                af[mi][2] = *(const unsigned*)(p + 16);
                af[mi][3] = *(const unsigned*)(p + 8 * LDSS + 16);
            }
            unsigned bf[4][2];
            #pragma unroll
            for (int ni = 0; ni < 4; ni++) {
                const signed char* p = sB + (wn * 32 + ni * 8 + (lane >> 2)) * LDSS + ks * 32 + (lane & 3) * 4;
                bf[ni][0] = *(const unsigned*)p;
                bf[ni][1] = *(const unsigned*)(p + 16);
            }
            #pragma unroll
            for (int mi = 0; mi < 4; mi++)
                #pragma unroll
                for (int ni = 0; ni < 4; ni++) mma8(acc[mi][ni], af[mi], bf[ni]);
        }
    }

    if (MODE == 1) {
        const float m1 = g_mval[2 + e];
        #pragma unroll
        for (int mi = 0; mi < 4; mi++) {
            #pragma unroll
            for (int half = 0; half < 2; half++) {
                int rrow = wm * 64 + mi * 16 + (lane >> 2) + half * 8;
                int pos = m0 + rrow;
                if (pos < cnt) {
                    float d = g_deqx[g_tok[e * TTOK + pos]] * m1;
                    float* hrow = g_h + (size_t)(off + pos) * HIDX + n0;
                    #pragma unroll
                    for (int ni = 0; ni < 4; ni++) {
                        int col = wn * 32 + ni * 8 + (lane & 3) * 2;
                        float2 v;
                        v.x = fmaxf(0.f, (float)acc[mi][ni][half * 2 + 0] * d);
                        v.y = fmaxf(0.f, (float)acc[mi][ni][half * 2 + 1] * d);
                        *(float2*)(hrow + col) = v;
                    }
                }
            }
        }
    } else {
        const float m2 = g_mval[10 + e];
        #pragma unroll
        for (int mi = 0; mi < 4; mi++) {
            #pragma unroll
            for (int half = 0; half < 2; half++) {
                int rrow = wm * 64 + mi * 16 + (lane >> 2) + half * 8;
                int pos = m0 + rrow;
                if (pos < cnt) {
                    int tok = g_tok[e * TTOK + pos];
                    float d = g_deqh[off + pos] * m2 * g_gate[e * TTOK + pos];
                    float* orow = out + (size_t)tok * DIMX + n0;
                    #pragma unroll
                    for (int ni = 0; ni < 4; ni++) {
                        int col = wn * 32 + ni * 8 + (lane & 3) * 2;
                        atomicAdd(orow + col, (float)acc[mi][ni][half * 2 + 0] * d);
                        atomicAdd(orow + col + 1, (float)acc[mi][ni][half * 2 + 1] * d);
                    }
                }
            }
        }
    }
}

// ---------------- launch ----------------
extern "C" void kernel_launch(void* const* d_in, const int* in_sizes, int n_in,
                              void* d_out, int out_size) {
    const float* x   = (const float*)d_in[0];
    const float* eps = (const float*)d_in[1];
    const float* wr  = (const float*)d_in[2];
    const float* wn  = (const float*)d_in[3];
    const float* w1  = (const float*)d_in[4];
    const float* w2  = (const float*)d_in[5];
    float* out = (float*)d_out;

    cudaMemsetAsync(d_out, 0, (size_t)out_size * sizeof(float));
    zero_cnt<<<1, 32>>>();
    stats_partial<<<dim3(64, 18), 256>>>(wr, wn, w1, w2);
    stats_final<<<1, 32>>>();
    wquant_small<<<64, 256>>>(wr, wn);
    wquant_big<<<32768, 256>>>(w1, 1);
    wquant_big<<<32768, 256>>>(w2, 2);
    act_quant<<<TTOK, 256>>>(x);
    router_kernel<<<TTOK / 8, 256>>>(eps);
    scan_off<<<1, 32>>>();
    bit_gemm<1><<<dim3(HIDX / BN, TTOK / BM, NEXP), 256>>>(nullptr);
    h_quant<<<dim3(TTOK, NEXP), 256>>>();
    bit_gemm<2><<<dim3(DIMX / BN, TTOK / BM, NEXP), 256>>>(out);
}